// round 4
// baseline (speedup 1.0000x reference)
#include <cuda_runtime.h>

// Problem constants
#define Bq   512
#define Tq   256
#define Fq   256
#define Hq   512
#define KTOT 768          // Hq + Fq  (fused [h | x_t] GEMM)
#define NG   2048         // 4*Hq gate columns

// Step-kernel tiling
#define BM      64        // batch rows per block
#define BJ      32        // hidden units per block
#define BCOLS   128       // gate columns per block = 4*BJ
#define BK      16        // K-tile
#define AP      68        // padded A smem row (floats), multiple of 4 for float4
#define NTHREADS 256      // 8 warps/block -> 2 warps per SMSP

// Persistent state (device globals: allocation-free per harness rules)
__device__ float g_h[2][Bq * Hq];
__device__ float g_c[Bq * Hq];

__device__ __forceinline__ float fsig(float x)  { return 1.0f / (1.0f + __expf(-x)); }
__device__ __forceinline__ float ftanh(float x) { return 2.0f / (1.0f + __expf(-2.0f * x)) - 1.0f; }

__global__ void zero_state_kernel() {
    int i = blockIdx.x * blockDim.x + threadIdx.x;
    const int n = Bq * Hq;
    for (; i < n; i += gridDim.x * blockDim.x) {
        g_h[0][i] = 0.0f;
        g_c[i]    = 0.0f;
    }
}

// Loader roles (256 threads):
//   A tile (BK x BM = 16x64 floats = 256 float4): lm = tid&63 (batch row),
//     kq = tid>>6 (0..3) -> one float4 at k-cols [kq*4, kq*4+4)
//   W tile (BK x BCOLS = 16x128 floats = 512 float4): wc = tid&127 (gate col),
//     half = tid>>7 (0/1) -> two float4 at k-cols [half*8, half*8+8)
__device__ __forceinline__ void prefetch_tile(
    int k0, int t, int m0, int lm, int kq, int wr, int half,
    const float* __restrict__ h_in, const float* __restrict__ x,
    const float* __restrict__ Whh,  const float* __restrict__ Wih,
    float4& a0, float4& w0, float4& w1)
{
    // A operand: rows = batch, cols = [h (0..511) | x_t (512..767)]
    const float* asrc = (k0 < Hq)
        ? h_in + (size_t)(m0 + lm) * Hq + k0 + kq * 4
        : x    + (size_t)(m0 + lm) * (Tq * Fq) + (size_t)t * Fq + (k0 - Hq) + kq * 4;
    a0 = *(const float4*)asrc;

    // W operand: row wr of [W_hh | W_ih]
    const float* wsrc = (k0 < Hq)
        ? Whh + (size_t)wr * Hq + k0 + half * 8
        : Wih + (size_t)wr * Fq + (k0 - Hq) + half * 8;
    w0 = *(const float4*)(wsrc);
    w1 = *(const float4*)(wsrc + 4);
}

// One LSTM timestep: gates = [h|x_t] @ [W_hh|W_ih]^T + b_ih + b_hh, then
// elementwise LSTM update fused into the epilogue.
// Grid: (NG/BCOLS, Bq/BM) = (16, 8) = 128 blocks, 256 threads each.
// Column layout inside a block (c in [0,128)): gate g = c&3, hidden j = j0 + (c>>2)
// => each thread (owning 8 consecutive c) holds i,f,g,o for 2 hidden units x 4 rows.
// Smem double-buffered: 1 BAR.SYNC per K-tile; stores of tile k+1 overlap FMAs on k.
__global__ __launch_bounds__(NTHREADS)
void lstm_step_kernel(const float* __restrict__ x,
                      const float* __restrict__ Wih,
                      const float* __restrict__ Whh,
                      const float* __restrict__ bih,
                      const float* __restrict__ bhh,
                      int t)
{
    const float* __restrict__ h_in  = g_h[t & 1];
    float* __restrict__       h_out = g_h[(t + 1) & 1];

    __shared__ float As[2][BK][AP];      // A tile, transposed: As[buf][k][m]
    __shared__ float Ws[2][BK][BCOLS];   // W tile, transposed: Ws[buf][k][c]

    const int tid = threadIdx.x;
    const int tr  = tid >> 4;   // 0..15 : row group (4 rows each)
    const int tc  = tid & 15;   // 0..15 : col group (8 cols each)
    const int m0  = blockIdx.y * BM;
    const int j0  = blockIdx.x * BJ;

    // Loader roles
    const int lm   = tid & 63;   // A row to load
    const int kq   = tid >> 6;   // which float4 (k-quad) of the A row
    const int wc   = tid & 127;  // W column to load
    const int half = tid >> 7;   // which 8-k half of the W column
    const int wr   = (wc & 3) * Hq + j0 + (wc >> 2);   // global weight row for col wc

    // Accumulators initialized with combined bias (b_ih + b_hh)
    float acc[4][8];
    #pragma unroll
    for (int u = 0; u < 8; u++) {
        const int c   = tc * 8 + u;
        const int row = (c & 3) * Hq + j0 + (c >> 2);
        const float bias = bih[row] + bhh[row];
        #pragma unroll
        for (int r = 0; r < 4; r++) acc[r][u] = bias;
    }

    const int NT = KTOT / BK;   // 48 K-tiles
    float4 pa0, pw0, pw1;

    // Prologue: load tile 0 into buffer 0
    prefetch_tile(0, t, m0, lm, kq, wr, half, h_in, x, Whh, Wih, pa0, pw0, pw1);
    {
        const float av[4] = {pa0.x, pa0.y, pa0.z, pa0.w};
        #pragma unroll
        for (int e = 0; e < 4; e++) As[0][kq * 4 + e][lm] = av[e];
        const float wv[8] = {pw0.x, pw0.y, pw0.z, pw0.w, pw1.x, pw1.y, pw1.z, pw1.w};
        #pragma unroll
        for (int e = 0; e < 8; e++) Ws[0][half * 8 + e][wc] = wv[e];
    }
    __syncthreads();

    for (int kt = 0; kt < NT; kt++) {
        const int cur = kt & 1;
        const int nxt = cur ^ 1;

        // Issue global prefetch of next tile early (hides L2 latency under FMAs)
        const bool have_next = (kt + 1 < NT);
        if (have_next)
            prefetch_tile((kt + 1) * BK, t, m0, lm, kq, wr, half, h_in, x, Whh, Wih,
                          pa0, pw0, pw1);

        // 16 x (4x8) FMA on current buffer
        #pragma unroll
        for (int k = 0; k < BK; k++) {
            const float4 a0 = *(const float4*)&As[cur][k][tr * 4];
            const float4 w0 = *(const float4*)&Ws[cur][k][tc * 8];
            const float4 w1 = *(const float4*)&Ws[cur][k][tc * 8 + 4];
            const float av[4] = {a0.x, a0.y, a0.z, a0.w};
            const float wv[8] = {w0.x, w0.y, w0.z, w0.w, w1.x, w1.y, w1.z, w1.w};
            #pragma unroll
            for (int r = 0; r < 4; r++)
                #pragma unroll
                for (int u = 0; u < 8; u++)
                    acc[r][u] += av[r] * wv[u];
        }

        // Store next tile into the other buffer, then one barrier
        if (have_next) {
            const float av[4] = {pa0.x, pa0.y, pa0.z, pa0.w};
            #pragma unroll
            for (int e = 0; e < 4; e++) As[nxt][kq * 4 + e][lm] = av[e];
            const float wv[8] = {pw0.x, pw0.y, pw0.z, pw0.w, pw1.x, pw1.y, pw1.z, pw1.w};
            #pragma unroll
            for (int e = 0; e < 8; e++) Ws[nxt][half * 8 + e][wc] = wv[e];
            __syncthreads();
        }
    }

    // Epilogue: acc[r][d*4+g] holds gate g for hidden unit j0 + tc*2 + d.
    #pragma unroll
    for (int r = 0; r < 4; r++) {
        const int m = m0 + tr * 4 + r;
        #pragma unroll
        for (int d = 0; d < 2; d++) {
            const int j = j0 + tc * 2 + d;
            const size_t idx = (size_t)m * Hq + j;
            const float ig = fsig (acc[r][d * 4 + 0]);
            const float fg = fsig (acc[r][d * 4 + 1]);
            const float gg = ftanh(acc[r][d * 4 + 2]);
            const float og = fsig (acc[r][d * 4 + 3]);
            const float cn = fg * g_c[idx] + ig * gg;
            g_c[idx]   = cn;
            h_out[idx] = og * ftanh(cn);
        }
    }
}

// out[b] = h_final[b,:] . W_out[0,:] + b_out[0]
__global__ void head_kernel(const float* __restrict__ Wout,
                            const float* __restrict__ bout,
                            float* __restrict__ out)
{
    const int b = blockIdx.x;
    const float* hrow = g_h[Tq & 1] + (size_t)b * Hq;   // T even -> final h in buffer 0
    float s = 0.0f;
    for (int k = threadIdx.x; k < Hq; k += blockDim.x)
        s += hrow[k] * Wout[k];
    __shared__ float red[32];
    #pragma unroll
    for (int o = 16; o; o >>= 1) s += __shfl_down_sync(0xffffffffu, s, o);
    if ((threadIdx.x & 31) == 0) red[threadIdx.x >> 5] = s;
    __syncthreads();
    if (threadIdx.x == 0)
        out[b] = red[0] + red[1] + red[2] + red[3] + bout[0];
}

extern "C" void kernel_launch(void* const* d_in, const int* in_sizes, int n_in,
                              void* d_out, int out_size)
{
    (void)in_sizes; (void)n_in; (void)out_size;
    const float* x    = (const float*)d_in[0];   // [B, T, F]
    const float* Wih  = (const float*)d_in[1];   // [4H, F]
    const float* Whh  = (const float*)d_in[2];   // [4H, H]
    const float* bih  = (const float*)d_in[3];   // [4H]
    const float* bhh  = (const float*)d_in[4];   // [4H]
    const float* Wout = (const float*)d_in[5];   // [O, H]
    const float* bout = (const float*)d_in[6];   // [O]
    float* out = (float*)d_out;                  // [B, O]

    zero_state_kernel<<<256, 256>>>();

    dim3 grid(NG / BCOLS, Bq / BM);              // (16, 8) = 128 blocks
    for (int t = 0; t < Tq; t++)
        lstm_step_kernel<<<grid, NTHREADS>>>(x, Wih, Whh, bih, bhh, t);

    head_kernel<<<Bq, 128>>>(Wout, bout, out);
}

// round 9
// speedup vs baseline: 2.5551x; 2.5551x over previous
#include <cuda_runtime.h>
#include <cuda_bf16.h>
#include <cstdint>

// Problem constants
#define Bq   512
#define Tq   256
#define Fq   256
#define Hq   512
#define KTOT 768
#define NG   2048          // 4*Hq gate columns (reordered: col' = 4*j + gate)

// Step GEMM tiling (mma.sync path — baseline PTX, no sm_100a features)
#define TM   128           // batch rows per CTA
#define TN   64            // gate cols per CTA (= 16 hidden units)
#define KC   32            // K elements per chunk
#define NKC  24            // KTOT / KC
#define NTH  256
#define RS   40            // smem row stride in bf16 elements (80 B, conflict-free ldmatrix)

// Smem stage layout (bytes): Ahi | Alo | Whi | Wlo
#define A_BYTES (TM * RS * 2)          // 10240
#define W_BYTES (TN * RS * 2)          // 5120
#define O_AHI 0
#define O_ALO (A_BYTES)
#define O_WHI (2 * A_BYTES)
#define O_WLO (2 * A_BYTES + W_BYTES)
#define STAGE_BYTES (2 * A_BYTES + 2 * W_BYTES)   // 30720
#define SMEM_BYTES (2 * STAGE_BYTES)              // 61440

// ---------------- persistent device state (no allocs allowed) ----------------
__device__ __nv_bfloat16 g_xhi[(size_t)Bq * Tq * Fq];
__device__ __nv_bfloat16 g_xlo[(size_t)Bq * Tq * Fq];
__device__ __nv_bfloat16 g_hhi[2][Bq * Hq];
__device__ __nv_bfloat16 g_hlo[2][Bq * Hq];
__device__ float         g_c[Bq * Hq];
__device__ __nv_bfloat16 g_Whi[NG * KTOT];   // reordered [col'][k]
__device__ __nv_bfloat16 g_Wlo[NG * KTOT];
__device__ float         g_br[NG];           // reordered combined bias

// ---------------- helpers ----------------
__device__ __forceinline__ uint32_t smem_u32(const void* p) {
    uint32_t a;
    asm("{ .reg .u64 t; cvta.to.shared.u64 t, %1; cvt.u32.u64 %0, t; }" : "=r"(a) : "l"(p));
    return a;
}
#define CP16(dst, src) \
    asm volatile("cp.async.cg.shared.global [%0], [%1], 16;" :: "r"(dst), "l"(src) : "memory")
#define CP_COMMIT() asm volatile("cp.async.commit_group;" ::: "memory")
#define CP_WAIT1()  asm volatile("cp.async.wait_group 1;" ::: "memory")
#define CP_WAIT0()  asm volatile("cp.async.wait_group 0;" ::: "memory")

__device__ __forceinline__ void ldsm4(uint32_t* r, uint32_t addr) {
    asm volatile("ldmatrix.sync.aligned.m8n8.x4.shared.b16 {%0,%1,%2,%3}, [%4];"
        : "=r"(r[0]), "=r"(r[1]), "=r"(r[2]), "=r"(r[3]) : "r"(addr));
}
__device__ __forceinline__ void mma16816(float* d, const uint32_t* a, const uint32_t* b) {
    asm volatile(
        "mma.sync.aligned.m16n8k16.row.col.f32.bf16.bf16.f32 "
        "{%0,%1,%2,%3}, {%4,%5,%6,%7}, {%8,%9}, {%0,%1,%2,%3};"
        : "+f"(d[0]), "+f"(d[1]), "+f"(d[2]), "+f"(d[3])
        : "r"(a[0]), "r"(a[1]), "r"(a[2]), "r"(a[3]), "r"(b[0]), "r"(b[1]));
}

__device__ __forceinline__ float fsig(float x)  { return 1.0f / (1.0f + __expf(-x)); }
__device__ __forceinline__ float ftanh(float x) { return 2.0f / (1.0f + __expf(-2.0f * x)) - 1.0f; }

// ---------------- prep kernels ----------------
__global__ void convert_x_kernel(const float* __restrict__ x) {
    size_t i = (size_t)blockIdx.x * blockDim.x + threadIdx.x;
    if (i >= (size_t)Bq * Tq * Fq) return;
    float v = x[i];
    __nv_bfloat16 hi = __float2bfloat16(v);
    g_xhi[i] = hi;
    g_xlo[i] = __float2bfloat16(v - __bfloat162float(hi));
}

__global__ void prep_w_kernel(const float* __restrict__ Wih, const float* __restrict__ Whh) {
    size_t i = (size_t)blockIdx.x * blockDim.x + threadIdx.x;
    if (i >= (size_t)NG * KTOT) return;
    int col = (int)(i / KTOT), k = (int)(i % KTOT);
    int r = (col & 3) * Hq + (col >> 2);            // original gate row (i,f,g,o blocks)
    float v = (k < Hq) ? Whh[(size_t)r * Hq + k] : Wih[(size_t)r * Fq + (k - Hq)];
    __nv_bfloat16 hi = __float2bfloat16(v);
    g_Whi[i] = hi;
    g_Wlo[i] = __float2bfloat16(v - __bfloat162float(hi));
}

__global__ void init_kernel(const float* __restrict__ bih, const float* __restrict__ bhh) {
    int i = blockIdx.x * blockDim.x + threadIdx.x;
    if (i < Bq * Hq) {
        g_hhi[0][i] = __float2bfloat16(0.0f);
        g_hlo[0][i] = __float2bfloat16(0.0f);
        g_c[i] = 0.0f;
    }
    if (i < NG) {
        int r = (i & 3) * Hq + (i >> 2);
        g_br[i] = bih[r] + bhh[r];
    }
}

// ---------------- chunk loader (cp.async, 16B segments) ----------------
__device__ __forceinline__ void load_chunk(
    int c, int t, int m0, int n0, int tid, uint32_t sb,
    const __nv_bfloat16* __restrict__ hhi, const __nv_bfloat16* __restrict__ hlo)
{
    const int k0 = c * KC;
    const uint32_t stg = sb + (c & 1) * STAGE_BYTES;
    // A: TM x KC = 512 segments of 16B, per hi/lo
    #pragma unroll
    for (int i = 0; i < 2; i++) {
        const int g = i * 256 + tid;
        const int row = g >> 2, seg = g & 3;
        const uint32_t d = (uint32_t)(row * (RS * 2) + seg * 16);
        const __nv_bfloat16 *sh, *sl;
        if (k0 < Hq) {
            const size_t o = (size_t)(m0 + row) * Hq + k0 + seg * 8;
            sh = hhi + o; sl = hlo + o;
        } else {
            const size_t o = ((size_t)(m0 + row) * Tq + t) * Fq + (k0 - Hq) + seg * 8;
            sh = g_xhi + o; sl = g_xlo + o;
        }
        CP16(stg + O_AHI + d, sh);
        CP16(stg + O_ALO + d, sl);
    }
    // W: TN x KC = 256 segments, per hi/lo
    {
        const int row = tid >> 2, seg = tid & 3;
        const uint32_t d = (uint32_t)(row * (RS * 2) + seg * 16);
        const size_t o = (size_t)(n0 + row) * KTOT + k0 + seg * 8;
        CP16(stg + O_WHI + d, g_Whi + o);
        CP16(stg + O_WLO + d, g_Wlo + o);
    }
    CP_COMMIT();
}

// ---------------- LSTM step: mma.sync bf16-split GEMM + fused epilogue ----------------
// Grid (32, 4): blockIdx.x = N-block (64 gate cols = 16 hidden), blockIdx.y = M-block.
// 8 warps: warpM = (wid&3)*32, warpN = (wid>>2)*32; warp tile 32m x 32n.
__global__ __launch_bounds__(NTH)
void lstm_step_kernel(int t)
{
    extern __shared__ char dyn_smem[];
    const uint32_t sb = smem_u32(dyn_smem);
    const int tid  = threadIdx.x;
    const int wid  = tid >> 5;
    const int lane = tid & 31;
    const int warpM = (wid & 3) * 32;
    const int warpN = (wid >> 2) * 32;

    const int m0 = blockIdx.y * TM;
    const int n0 = blockIdx.x * TN;

    const __nv_bfloat16* __restrict__ hhi = g_hhi[t & 1];
    const __nv_bfloat16* __restrict__ hlo = g_hlo[t & 1];
    __nv_bfloat16* __restrict__ hhi_o = g_hhi[(t + 1) & 1];
    __nv_bfloat16* __restrict__ hlo_o = g_hlo[(t + 1) & 1];

    float acc[2][4][4];
    #pragma unroll
    for (int mi = 0; mi < 2; mi++)
        #pragma unroll
        for (int nj = 0; nj < 4; nj++)
            #pragma unroll
            for (int r = 0; r < 4; r++) acc[mi][nj][r] = 0.0f;

    load_chunk(0, t, m0, n0, tid, sb, hhi, hlo);

    for (int c = 0; c < NKC; c++) {
        if (c + 1 < NKC) { load_chunk(c + 1, t, m0, n0, tid, sb, hhi, hlo); CP_WAIT1(); }
        else             { CP_WAIT0(); }
        __syncthreads();

        const uint32_t stg = sb + (c & 1) * STAGE_BYTES;
        const uint32_t aBase[3] = {stg + O_AHI, stg + O_ALO, stg + O_AHI};
        const uint32_t wBase[3] = {stg + O_WHI, stg + O_WHI, stg + O_WLO};

        #pragma unroll
        for (int p = 0; p < 3; p++) {
            #pragma unroll
            for (int kk = 0; kk < 2; kk++) {
                uint32_t a[2][4];
                #pragma unroll
                for (int mi = 0; mi < 2; mi++) {
                    const int row = warpM + mi * 16 + (lane & 15);
                    const int k   = kk * 16 + (lane >> 4) * 8;
                    ldsm4(a[mi], aBase[p] + (uint32_t)((row * RS + k) * 2));
                }
                uint32_t b[2][4];   // b[g2]: {b0,b1} of nj=2g2, {b0,b1} of nj=2g2+1
                #pragma unroll
                for (int g2 = 0; g2 < 2; g2++) {
                    const int n = warpN + g2 * 16 + ((lane >> 4) & 1) * 8 + (lane & 7);
                    const int k = kk * 16 + ((lane >> 3) & 1) * 8;
                    ldsm4(b[g2], wBase[p] + (uint32_t)((n * RS + k) * 2));
                }
                #pragma unroll
                for (int mi = 0; mi < 2; mi++)
                    #pragma unroll
                    for (int nj = 0; nj < 4; nj++)
                        mma16816(acc[mi][nj], a[mi], &b[nj >> 1][(nj & 1) * 2]);
            }
        }
        __syncthreads();   // protect stage (c&1) before it is refilled at c+2
    }

    // ---- fused LSTM epilogue ----
    // c-frag of m16n8: c0=(r,col), c1=(r,col+1), c2=(r+8,col), c3=(r+8,col+1),
    // r = lane>>2, col = (lane&3)*2. With col'=4j+g, lane pair (l, l^1) holds
    // all 4 gates of one hidden unit j; shfl_xor(1) exchanges the halves.
    const int q = lane & 3;
    #pragma unroll
    for (int mi = 0; mi < 2; mi++) {
        #pragma unroll
        for (int nj = 0; nj < 4; nj++) {
            float* cr = acc[mi][nj];
            const float e0 = __shfl_xor_sync(0xffffffffu, cr[0], 1);
            const float e1 = __shfl_xor_sync(0xffffffffu, cr[1], 1);
            const float e2 = __shfl_xor_sync(0xffffffffu, cr[2], 1);
            const float e3 = __shfl_xor_sync(0xffffffffu, cr[3], 1);
            const int nb = n0 + warpN + nj * 8 + (q >> 1) * 4;
            const float4 bb = *(const float4*)&g_br[nb];
            const int j = nb >> 2;
            float ri, rf, rg, ro;
            int m = m0 + warpM + mi * 16 + (lane >> 2);
            if ((lane & 1) == 0) { ri = cr[0]; rf = cr[1]; rg = e0;   ro = e1;   }
            else                 { ri = e2;    rf = e3;    rg = cr[2]; ro = cr[3]; m += 8; }
            const float ig = fsig (ri + bb.x);
            const float fg = fsig (rf + bb.y);
            const float gg = ftanh(rg + bb.z);
            const float og = fsig (ro + bb.w);
            const size_t idx = (size_t)m * Hq + j;
            const float cn = fg * g_c[idx] + ig * gg;
            g_c[idx] = cn;
            const float hv = og * ftanh(cn);
            const __nv_bfloat16 hh = __float2bfloat16(hv);
            hhi_o[idx] = hh;
            hlo_o[idx] = __float2bfloat16(hv - __bfloat162float(hh));
        }
    }
}

// out[b] = h_final[b,:] . W_out[0,:] + b_out[0]
__global__ void head_kernel(const float* __restrict__ Wout,
                            const float* __restrict__ bout,
                            float* __restrict__ out)
{
    const int b = blockIdx.x;
    const __nv_bfloat16* hi = g_hhi[0] + (size_t)b * Hq;   // T even -> final h in buffer 0
    const __nv_bfloat16* lo = g_hlo[0] + (size_t)b * Hq;
    float s = 0.0f;
    for (int k = threadIdx.x; k < Hq; k += blockDim.x)
        s += (__bfloat162float(hi[k]) + __bfloat162float(lo[k])) * Wout[k];
    __shared__ float red[32];
    #pragma unroll
    for (int o = 16; o; o >>= 1) s += __shfl_down_sync(0xffffffffu, s, o);
    if ((threadIdx.x & 31) == 0) red[threadIdx.x >> 5] = s;
    __syncthreads();
    if (threadIdx.x == 0)
        out[b] = red[0] + red[1] + red[2] + red[3] + bout[0];
}

extern "C" void kernel_launch(void* const* d_in, const int* in_sizes, int n_in,
                              void* d_out, int out_size)
{
    (void)in_sizes; (void)n_in; (void)out_size;
    const float* x    = (const float*)d_in[0];
    const float* Wih  = (const float*)d_in[1];
    const float* Whh  = (const float*)d_in[2];
    const float* bih  = (const float*)d_in[3];
    const float* bhh  = (const float*)d_in[4];
    const float* Wout = (const float*)d_in[5];
    const float* bout = (const float*)d_in[6];
    float* out = (float*)d_out;

    cudaFuncSetAttribute(lstm_step_kernel,
                         cudaFuncAttributeMaxDynamicSharedMemorySize, SMEM_BYTES);

    {
        const size_t n = (size_t)Bq * Tq * Fq;
        convert_x_kernel<<<(unsigned)((n + 255) / 256), 256>>>(x);
    }
    {
        const size_t n = (size_t)NG * KTOT;
        prep_w_kernel<<<(unsigned)((n + 255) / 256), 256>>>(Wih, Whh);
    }
    init_kernel<<<(Bq * Hq + 255) / 256, 256>>>(bih, bhh);

    dim3 grid(NG / TN, Bq / TM);   // (32, 4) = 128 CTAs
    for (int t = 0; t < Tq; t++)
        lstm_step_kernel<<<grid, NTH, SMEM_BYTES>>>(t);

    head_kernel<<<Bq, 128>>>(Wout, bout, out);
}

// round 12
// speedup vs baseline: 2.6770x; 1.0477x over previous
#include <cuda_runtime.h>
#include <cuda_bf16.h>
#include <cstdint>

// Problem constants
#define Bq   512
#define Tq   256
#define Fq   256
#define Hq   512
#define KTOT 768
#define NG   2048          // 4*Hq gate columns (reordered: col' = 4*j + gate)

// Step GEMM tiling (mma.sync path — baseline PTX, no sm_100a features)
#define TM   128           // batch rows per CTA
#define TN   64            // gate cols per CTA (= 16 hidden units)
#define KC   32            // K elements per chunk
#define NKC  24            // KTOT / KC
#define NTH  256
#define RS   40            // smem row stride in bf16 elements (80 B, conflict-free ldmatrix)
#define NSTG 4             // pipeline stages (prefetch depth 3)

// Smem stage layout (bytes): Ahi | Alo | Whi | Wlo
#define A_BYTES (TM * RS * 2)          // 10240
#define W_BYTES (TN * RS * 2)          // 5120
#define O_AHI 0
#define O_ALO (A_BYTES)
#define O_WHI (2 * A_BYTES)
#define O_WLO (2 * A_BYTES + W_BYTES)
#define STAGE_BYTES (2 * A_BYTES + 2 * W_BYTES)   // 30720
#define SMEM_BYTES (NSTG * STAGE_BYTES)           // 122880

// ---------------- persistent device state (no allocs allowed) ----------------
__device__ __nv_bfloat16 g_xhi[(size_t)Bq * Tq * Fq];
__device__ __nv_bfloat16 g_xlo[(size_t)Bq * Tq * Fq];
__device__ __nv_bfloat16 g_hhi[2][Bq * Hq];
__device__ __nv_bfloat16 g_hlo[2][Bq * Hq];
__device__ float         g_c[Bq * Hq];
__device__ __nv_bfloat16 g_Whi[NG * KTOT];   // reordered [col'][k]
__device__ __nv_bfloat16 g_Wlo[NG * KTOT];
__device__ float         g_br[NG];           // reordered combined bias

// ---------------- helpers ----------------
__device__ __forceinline__ uint32_t smem_u32(const void* p) {
    uint32_t a;
    asm("{ .reg .u64 t; cvta.to.shared.u64 t, %1; cvt.u32.u64 %0, t; }" : "=r"(a) : "l"(p));
    return a;
}
#define CP16(dst, src) \
    asm volatile("cp.async.cg.shared.global [%0], [%1], 16;" :: "r"(dst), "l"(src) : "memory")
#define CP_COMMIT() asm volatile("cp.async.commit_group;" ::: "memory")
#define CP_WAIT3()  asm volatile("cp.async.wait_group 3;" ::: "memory")
#define CP_WAIT2()  asm volatile("cp.async.wait_group 2;" ::: "memory")
#define CP_WAIT1()  asm volatile("cp.async.wait_group 1;" ::: "memory")
#define CP_WAIT0()  asm volatile("cp.async.wait_group 0;" ::: "memory")

__device__ __forceinline__ void ldsm4(uint32_t* r, uint32_t addr) {
    asm volatile("ldmatrix.sync.aligned.m8n8.x4.shared.b16 {%0,%1,%2,%3}, [%4];"
        : "=r"(r[0]), "=r"(r[1]), "=r"(r[2]), "=r"(r[3]) : "r"(addr));
}
__device__ __forceinline__ void mma16816(float* d, const uint32_t* a, const uint32_t* b) {
    asm volatile(
        "mma.sync.aligned.m16n8k16.row.col.f32.bf16.bf16.f32 "
        "{%0,%1,%2,%3}, {%4,%5,%6,%7}, {%8,%9}, {%0,%1,%2,%3};"
        : "+f"(d[0]), "+f"(d[1]), "+f"(d[2]), "+f"(d[3])
        : "r"(a[0]), "r"(a[1]), "r"(a[2]), "r"(a[3]), "r"(b[0]), "r"(b[1]));
}

__device__ __forceinline__ float fsig(float x)  { return 1.0f / (1.0f + __expf(-x)); }
__device__ __forceinline__ float ftanh(float x) { return 2.0f / (1.0f + __expf(-2.0f * x)) - 1.0f; }

// ---------------- prep kernels ----------------
__global__ void convert_x_kernel(const float* __restrict__ x) {
    size_t i = (size_t)blockIdx.x * blockDim.x + threadIdx.x;
    if (i >= (size_t)Bq * Tq * Fq) return;
    float v = x[i];
    __nv_bfloat16 hi = __float2bfloat16(v);
    g_xhi[i] = hi;
    g_xlo[i] = __float2bfloat16(v - __bfloat162float(hi));
}

__global__ void prep_w_kernel(const float* __restrict__ Wih, const float* __restrict__ Whh) {
    size_t i = (size_t)blockIdx.x * blockDim.x + threadIdx.x;
    if (i >= (size_t)NG * KTOT) return;
    int col = (int)(i / KTOT), k = (int)(i % KTOT);
    int r = (col & 3) * Hq + (col >> 2);            // original gate row (i,f,g,o blocks)
    float v = (k < Hq) ? Whh[(size_t)r * Hq + k] : Wih[(size_t)r * Fq + (k - Hq)];
    __nv_bfloat16 hi = __float2bfloat16(v);
    g_Whi[i] = hi;
    g_Wlo[i] = __float2bfloat16(v - __bfloat162float(hi));
}

__global__ void init_kernel(const float* __restrict__ bih, const float* __restrict__ bhh) {
    int i = blockIdx.x * blockDim.x + threadIdx.x;
    if (i < Bq * Hq) {
        g_hhi[0][i] = __float2bfloat16(0.0f);
        g_hlo[0][i] = __float2bfloat16(0.0f);
        g_c[i] = 0.0f;
    }
    if (i < NG) {
        int r = (i & 3) * Hq + (i >> 2);
        g_br[i] = bih[r] + bhh[r];
    }
}

// ---------------- chunk loader (cp.async, 16B segments) ----------------
__device__ __forceinline__ void load_chunk(
    int c, int t, int m0, int n0, int tid, uint32_t sb,
    const __nv_bfloat16* __restrict__ hhi, const __nv_bfloat16* __restrict__ hlo)
{
    const int k0 = c * KC;
    const uint32_t stg = sb + (uint32_t)(c & (NSTG - 1)) * STAGE_BYTES;
    // A: TM x KC = 512 segments of 16B, per hi/lo
    #pragma unroll
    for (int i = 0; i < 2; i++) {
        const int g = i * 256 + tid;
        const int row = g >> 2, seg = g & 3;
        const uint32_t d = (uint32_t)(row * (RS * 2) + seg * 16);
        const __nv_bfloat16 *sh, *sl;
        if (k0 < Hq) {
            const size_t o = (size_t)(m0 + row) * Hq + k0 + seg * 8;
            sh = hhi + o; sl = hlo + o;
        } else {
            const size_t o = ((size_t)(m0 + row) * Tq + t) * Fq + (k0 - Hq) + seg * 8;
            sh = g_xhi + o; sl = g_xlo + o;
        }
        CP16(stg + O_AHI + d, sh);
        CP16(stg + O_ALO + d, sl);
    }
    // W: TN x KC = 256 segments, per hi/lo
    {
        const int row = tid >> 2, seg = tid & 3;
        const uint32_t d = (uint32_t)(row * (RS * 2) + seg * 16);
        const size_t o = (size_t)(n0 + row) * KTOT + k0 + seg * 8;
        CP16(stg + O_WHI + d, g_Whi + o);
        CP16(stg + O_WLO + d, g_Wlo + o);
    }
    CP_COMMIT();
}

// ---------------- LSTM step: mma.sync bf16-split GEMM + fused epilogue ----------------
// Grid (32, 4): blockIdx.x = N-block (64 gate cols = 16 hidden), blockIdx.y = M-block.
// 8 warps: warpM = (wid&3)*32, warpN = (wid>>2)*32; warp tile 32m x 32n.
// 4-stage cp.async pipeline (prefetch depth 3); per k16 all four fragment sets
// are loaded once (8 ldsm) and 24 MMAs issued (hi*Whi, lo*Whi, hi*Wlo).
__global__ __launch_bounds__(NTH)
void lstm_step_kernel(int t)
{
    extern __shared__ char dyn_smem[];
    const uint32_t sb = smem_u32(dyn_smem);
    const int tid  = threadIdx.x;
    const int wid  = tid >> 5;
    const int lane = tid & 31;
    const int warpM = (wid & 3) * 32;
    const int warpN = (wid >> 2) * 32;

    const int m0 = blockIdx.y * TM;
    const int n0 = blockIdx.x * TN;

    const __nv_bfloat16* __restrict__ hhi = g_hhi[t & 1];
    const __nv_bfloat16* __restrict__ hlo = g_hlo[t & 1];
    __nv_bfloat16* __restrict__ hhi_o = g_hhi[(t + 1) & 1];
    __nv_bfloat16* __restrict__ hlo_o = g_hlo[(t + 1) & 1];

    float acc[2][4][4];
    #pragma unroll
    for (int mi = 0; mi < 2; mi++)
        #pragma unroll
        for (int nj = 0; nj < 4; nj++)
            #pragma unroll
            for (int r = 0; r < 4; r++) acc[mi][nj][r] = 0.0f;

    // Prologue: fill 3 stages
    load_chunk(0, t, m0, n0, tid, sb, hhi, hlo);
    load_chunk(1, t, m0, n0, tid, sb, hhi, hlo);
    load_chunk(2, t, m0, n0, tid, sb, hhi, hlo);

    // Precomputed per-warp ldsm address offsets (element indices)
    const int aRowOff = (lane & 15) * RS + (lane >> 4) * 8;          // + mi*16*RS + kk*16
    const int wRowOff = (((lane >> 4) & 1) * 8 + (lane & 7)) * RS + ((lane >> 3) & 1) * 8;

    for (int c = 0; c < NKC; c++) {
        // Prefetch chunk c+3 into the stage freed by compute(c-1)
        // (trailing barrier of iter c-1 makes this race-free).
        if (c + 3 < NKC) load_chunk(c + 3, t, m0, n0, tid, sb, hhi, hlo);

        // Wait until chunk c is resident: allow min(3, NKC-1-c) newer groups.
        const int rem = NKC - 1 - c;
        if (rem >= 3)      CP_WAIT3();
        else if (rem == 2) CP_WAIT2();
        else if (rem == 1) CP_WAIT1();
        else               CP_WAIT0();
        __syncthreads();

        const uint32_t stg = sb + (uint32_t)(c & (NSTG - 1)) * STAGE_BYTES;
        #pragma unroll
        for (int kk = 0; kk < 2; kk++) {
            uint32_t ah[2][4], al[2][4], wh[2][4], wl[2][4];
            #pragma unroll
            for (int mi = 0; mi < 2; mi++) {
                const uint32_t off = (uint32_t)((warpM + mi * 16) * RS + kk * 16 + aRowOff) * 2;
                ldsm4(ah[mi], stg + O_AHI + off);
                ldsm4(al[mi], stg + O_ALO + off);
            }
            #pragma unroll
            for (int g2 = 0; g2 < 2; g2++) {
                const uint32_t off = (uint32_t)((warpN + g2 * 16) * RS + kk * 16 + wRowOff) * 2;
                ldsm4(wh[g2], stg + O_WHI + off);
                ldsm4(wl[g2], stg + O_WLO + off);
            }
            #pragma unroll
            for (int mi = 0; mi < 2; mi++)
                #pragma unroll
                for (int nj = 0; nj < 4; nj++)
                    mma16816(acc[mi][nj], ah[mi], &wh[nj >> 1][(nj & 1) * 2]);
            #pragma unroll
            for (int mi = 0; mi < 2; mi++)
                #pragma unroll
                for (int nj = 0; nj < 4; nj++)
                    mma16816(acc[mi][nj], al[mi], &wh[nj >> 1][(nj & 1) * 2]);
            #pragma unroll
            for (int mi = 0; mi < 2; mi++)
                #pragma unroll
                for (int nj = 0; nj < 4; nj++)
                    mma16816(acc[mi][nj], ah[mi], &wl[nj >> 1][(nj & 1) * 2]);
        }
        __syncthreads();   // compute(c) done before iter c+1 refills stage (c+4)%4 = c%4
    }

    // ---- fused LSTM epilogue ----
    // c-frag of m16n8: c0=(r,col), c1=(r,col+1), c2=(r+8,col), c3=(r+8,col+1),
    // r = lane>>2, col = (lane&3)*2. With col'=4j+g, lane pair (l, l^1) holds
    // all 4 gates of one hidden unit j; shfl_xor(1) exchanges the halves.
    const int q = lane & 3;
    #pragma unroll
    for (int mi = 0; mi < 2; mi++) {
        #pragma unroll
        for (int nj = 0; nj < 4; nj++) {
            float* cr = acc[mi][nj];
            const float e0 = __shfl_xor_sync(0xffffffffu, cr[0], 1);
            const float e1 = __shfl_xor_sync(0xffffffffu, cr[1], 1);
            const float e2 = __shfl_xor_sync(0xffffffffu, cr[2], 1);
            const float e3 = __shfl_xor_sync(0xffffffffu, cr[3], 1);
            const int nb = n0 + warpN + nj * 8 + (q >> 1) * 4;
            const float4 bb = *(const float4*)&g_br[nb];
            const int j = nb >> 2;
            float ri, rf, rg, ro;
            int m = m0 + warpM + mi * 16 + (lane >> 2);
            if ((lane & 1) == 0) { ri = cr[0]; rf = cr[1]; rg = e0;   ro = e1;   }
            else                 { ri = e2;    rf = e3;    rg = cr[2]; ro = cr[3]; m += 8; }
            const float ig = fsig (ri + bb.x);
            const float fg = fsig (rf + bb.y);
            const float gg = ftanh(rg + bb.z);
            const float og = fsig (ro + bb.w);
            const size_t idx = (size_t)m * Hq + j;
            const float cn = fg * g_c[idx] + ig * gg;
            g_c[idx] = cn;
            const float hv = og * ftanh(cn);
            const __nv_bfloat16 hh = __float2bfloat16(hv);
            hhi_o[idx] = hh;
            hlo_o[idx] = __float2bfloat16(hv - __bfloat162float(hh));
        }
    }
}

// out[b] = h_final[b,:] . W_out[0,:] + b_out[0]
__global__ void head_kernel(const float* __restrict__ Wout,
                            const float* __restrict__ bout,
                            float* __restrict__ out)
{
    const int b = blockIdx.x;
    const __nv_bfloat16* hi = g_hhi[0] + (size_t)b * Hq;   // T even -> final h in buffer 0
    const __nv_bfloat16* lo = g_hlo[0] + (size_t)b * Hq;
    float s = 0.0f;
    for (int k = threadIdx.x; k < Hq; k += blockDim.x)
        s += (__bfloat162float(hi[k]) + __bfloat162float(lo[k])) * Wout[k];
    __shared__ float red[32];
    #pragma unroll
    for (int o = 16; o; o >>= 1) s += __shfl_down_sync(0xffffffffu, s, o);
    if ((threadIdx.x & 31) == 0) red[threadIdx.x >> 5] = s;
    __syncthreads();
    if (threadIdx.x == 0)
        out[b] = red[0] + red[1] + red[2] + red[3] + bout[0];
}

extern "C" void kernel_launch(void* const* d_in, const int* in_sizes, int n_in,
                              void* d_out, int out_size)
{
    (void)in_sizes; (void)n_in; (void)out_size;
    const float* x    = (const float*)d_in[0];
    const float* Wih  = (const float*)d_in[1];
    const float* Whh  = (const float*)d_in[2];
    const float* bih  = (const float*)d_in[3];
    const float* bhh  = (const float*)d_in[4];
    const float* Wout = (const float*)d_in[5];
    const float* bout = (const float*)d_in[6];
    float* out = (float*)d_out;

    cudaFuncSetAttribute(lstm_step_kernel,
                         cudaFuncAttributeMaxDynamicSharedMemorySize, SMEM_BYTES);

    {
        const size_t n = (size_t)Bq * Tq * Fq;
        convert_x_kernel<<<(unsigned)((n + 255) / 256), 256>>>(x);
    }
    {
        const size_t n = (size_t)NG * KTOT;
        prep_w_kernel<<<(unsigned)((n + 255) / 256), 256>>>(Wih, Whh);
    }
    init_kernel<<<(Bq * Hq + 255) / 256, 256>>>(bih, bhh);

    dim3 grid(NG / TN, Bq / TM);   // (32, 4) = 128 CTAs
    for (int t = 0; t < Tq; t++)
        lstm_step_kernel<<<grid, NTH, SMEM_BYTES>>>(t);

    head_kernel<<<Bq, 128>>>(Wout, bout, out);
}

// round 13
// speedup vs baseline: 3.1008x; 1.1583x over previous
#include <cuda_runtime.h>
#include <cuda_bf16.h>
#include <cstdint>

// Problem constants
#define Bq   512
#define Tq   256
#define Fq   256
#define Hq   512
#define KTOT 768
#define NG   2048          // 4*Hq gate columns (reordered: col' = 4*j + gate)

// Step GEMM tiling (mma.sync path — baseline PTX, no sm_100a features)
#define TM   64            // batch rows per CTA
#define TN   64            // gate cols per CTA (= 16 hidden units)
#define KC   32            // K elements per chunk
#define NKC  24            // KTOT / KC
#define NTH  256
#define RS   40            // smem row stride in bf16 elements (80 B, conflict-free ldmatrix)
#define NSTG 4             // pipeline stages (prefetch depth 3)

// Smem stage layout (bytes): Ahi | Alo | Whi | Wlo
#define A_BYTES (TM * RS * 2)          // 5120
#define W_BYTES (TN * RS * 2)          // 5120
#define O_AHI 0
#define O_ALO (A_BYTES)
#define O_WHI (2 * A_BYTES)
#define O_WLO (2 * A_BYTES + W_BYTES)
#define STAGE_BYTES (2 * A_BYTES + 2 * W_BYTES)   // 20480
#define SMEM_BYTES (NSTG * STAGE_BYTES)           // 81920  (2 CTAs/SM: 160K < 227K)

// ---------------- persistent device state (no allocs allowed) ----------------
__device__ __nv_bfloat16 g_xhi[(size_t)Bq * Tq * Fq];
__device__ __nv_bfloat16 g_xlo[(size_t)Bq * Tq * Fq];
__device__ __nv_bfloat16 g_hhi[2][Bq * Hq];
__device__ __nv_bfloat16 g_hlo[2][Bq * Hq];
__device__ float         g_c[Bq * Hq];
__device__ __nv_bfloat16 g_Whi[NG * KTOT];   // reordered [col'][k]
__device__ __nv_bfloat16 g_Wlo[NG * KTOT];
__device__ float         g_br[NG];           // reordered combined bias

// ---------------- helpers ----------------
__device__ __forceinline__ uint32_t smem_u32(const void* p) {
    uint32_t a;
    asm("{ .reg .u64 t; cvta.to.shared.u64 t, %1; cvt.u32.u64 %0, t; }" : "=r"(a) : "l"(p));
    return a;
}
#define CP16(dst, src) \
    asm volatile("cp.async.cg.shared.global [%0], [%1], 16;" :: "r"(dst), "l"(src) : "memory")
#define CP_COMMIT() asm volatile("cp.async.commit_group;" ::: "memory")
#define CP_WAIT3()  asm volatile("cp.async.wait_group 3;" ::: "memory")
#define CP_WAIT2()  asm volatile("cp.async.wait_group 2;" ::: "memory")
#define CP_WAIT1()  asm volatile("cp.async.wait_group 1;" ::: "memory")
#define CP_WAIT0()  asm volatile("cp.async.wait_group 0;" ::: "memory")

__device__ __forceinline__ void ldsm4(uint32_t* r, uint32_t addr) {
    asm volatile("ldmatrix.sync.aligned.m8n8.x4.shared.b16 {%0,%1,%2,%3}, [%4];"
        : "=r"(r[0]), "=r"(r[1]), "=r"(r[2]), "=r"(r[3]) : "r"(addr));
}
__device__ __forceinline__ void mma16816(float* d, const uint32_t* a, const uint32_t* b) {
    asm volatile(
        "mma.sync.aligned.m16n8k16.row.col.f32.bf16.bf16.f32 "
        "{%0,%1,%2,%3}, {%4,%5,%6,%7}, {%8,%9}, {%0,%1,%2,%3};"
        : "+f"(d[0]), "+f"(d[1]), "+f"(d[2]), "+f"(d[3])
        : "r"(a[0]), "r"(a[1]), "r"(a[2]), "r"(a[3]), "r"(b[0]), "r"(b[1]));
}

__device__ __forceinline__ float fsig(float x)  { return 1.0f / (1.0f + __expf(-x)); }
__device__ __forceinline__ float ftanh(float x) { return 2.0f / (1.0f + __expf(-2.0f * x)) - 1.0f; }

// ---------------- prep kernels ----------------
__global__ void convert_x_kernel(const float* __restrict__ x) {
    size_t i = (size_t)blockIdx.x * blockDim.x + threadIdx.x;
    if (i >= (size_t)Bq * Tq * Fq) return;
    float v = x[i];
    __nv_bfloat16 hi = __float2bfloat16(v);
    g_xhi[i] = hi;
    g_xlo[i] = __float2bfloat16(v - __bfloat162float(hi));
}

__global__ void prep_w_kernel(const float* __restrict__ Wih, const float* __restrict__ Whh) {
    size_t i = (size_t)blockIdx.x * blockDim.x + threadIdx.x;
    if (i >= (size_t)NG * KTOT) return;
    int col = (int)(i / KTOT), k = (int)(i % KTOT);
    int r = (col & 3) * Hq + (col >> 2);            // original gate row (i,f,g,o blocks)
    float v = (k < Hq) ? Whh[(size_t)r * Hq + k] : Wih[(size_t)r * Fq + (k - Hq)];
    __nv_bfloat16 hi = __float2bfloat16(v);
    g_Whi[i] = hi;
    g_Wlo[i] = __float2bfloat16(v - __bfloat162float(hi));
}

__global__ void init_kernel(const float* __restrict__ bih, const float* __restrict__ bhh) {
    int i = blockIdx.x * blockDim.x + threadIdx.x;
    if (i < Bq * Hq) {
        g_hhi[0][i] = __float2bfloat16(0.0f);
        g_hlo[0][i] = __float2bfloat16(0.0f);
        g_c[i] = 0.0f;
    }
    if (i < NG) {
        int r = (i & 3) * Hq + (i >> 2);
        g_br[i] = bih[r] + bhh[r];
    }
}

// ---------------- chunk loader (cp.async, 16B segments; 1 segment/tile/thread) ----------------
__device__ __forceinline__ void load_chunk(
    int c, int t, int m0, int n0, int tid, uint32_t sb,
    const __nv_bfloat16* __restrict__ hhi, const __nv_bfloat16* __restrict__ hlo)
{
    const int k0 = c * KC;
    const uint32_t stg = sb + (uint32_t)(c & (NSTG - 1)) * STAGE_BYTES;
    const int row = tid >> 2, seg = tid & 3;              // 64 rows x 4 x 16B
    const uint32_t d = (uint32_t)(row * (RS * 2) + seg * 16);
    // A: TM x KC, hi/lo
    {
        const __nv_bfloat16 *sh, *sl;
        if (k0 < Hq) {
            const size_t o = (size_t)(m0 + row) * Hq + k0 + seg * 8;
            sh = hhi + o; sl = hlo + o;
        } else {
            const size_t o = ((size_t)(m0 + row) * Tq + t) * Fq + (k0 - Hq) + seg * 8;
            sh = g_xhi + o; sl = g_xlo + o;
        }
        CP16(stg + O_AHI + d, sh);
        CP16(stg + O_ALO + d, sl);
    }
    // W: TN x KC, hi/lo
    {
        const size_t o = (size_t)(n0 + row) * KTOT + k0 + seg * 8;
        CP16(stg + O_WHI + d, g_Whi + o);
        CP16(stg + O_WLO + d, g_Wlo + o);
    }
    CP_COMMIT();
}

// ---------------- LSTM step: mma.sync bf16-split GEMM + fused epilogue ----------------
// Grid (32, 8): blockIdx.x = N-block (64 gate cols = 16 hidden), blockIdx.y = M-block.
// 2 CTAs/SM (256 CTAs, 80KB smem each) -> 16 warps/SM, two independent barrier
// domains per SM so one CTA's compute hides the other's barriers/latency.
// 8 warps: warpM = (wid&1)*32, warpN = (wid>>1)*16; warp tile 32m x 16n.
__global__ __launch_bounds__(NTH, 2)
void lstm_step_kernel(int t)
{
    extern __shared__ char dyn_smem[];
    const uint32_t sb = smem_u32(dyn_smem);
    const int tid  = threadIdx.x;
    const int wid  = tid >> 5;
    const int lane = tid & 31;
    const int warpM = (wid & 1) * 32;
    const int warpN = (wid >> 1) * 16;

    const int m0 = blockIdx.y * TM;
    const int n0 = blockIdx.x * TN;

    const __nv_bfloat16* __restrict__ hhi = g_hhi[t & 1];
    const __nv_bfloat16* __restrict__ hlo = g_hlo[t & 1];
    __nv_bfloat16* __restrict__ hhi_o = g_hhi[(t + 1) & 1];
    __nv_bfloat16* __restrict__ hlo_o = g_hlo[(t + 1) & 1];

    float acc[2][2][4];
    #pragma unroll
    for (int mi = 0; mi < 2; mi++)
        #pragma unroll
        for (int nj = 0; nj < 2; nj++)
            #pragma unroll
            for (int r = 0; r < 4; r++) acc[mi][nj][r] = 0.0f;

    // Prologue: fill 3 stages
    load_chunk(0, t, m0, n0, tid, sb, hhi, hlo);
    load_chunk(1, t, m0, n0, tid, sb, hhi, hlo);
    load_chunk(2, t, m0, n0, tid, sb, hhi, hlo);

    // Precomputed per-warp ldsm address offsets (element indices)
    const int aRowOff = (lane & 15) * RS + (lane >> 4) * 8;          // + mi*16*RS + kk*16
    const int wRowOff = (((lane >> 4) & 1) * 8 + (lane & 7)) * RS + ((lane >> 3) & 1) * 8;

    for (int c = 0; c < NKC; c++) {
        // Prefetch chunk c+3 into the stage freed by compute(c-1)
        // (trailing barrier of iter c-1 makes this race-free).
        if (c + 3 < NKC) load_chunk(c + 3, t, m0, n0, tid, sb, hhi, hlo);

        // Wait until chunk c is resident: allow min(3, NKC-1-c) newer groups.
        const int rem = NKC - 1 - c;
        if (rem >= 3)      CP_WAIT3();
        else if (rem == 2) CP_WAIT2();
        else if (rem == 1) CP_WAIT1();
        else               CP_WAIT0();
        __syncthreads();

        const uint32_t stg = sb + (uint32_t)(c & (NSTG - 1)) * STAGE_BYTES;
        #pragma unroll
        for (int kk = 0; kk < 2; kk++) {
            uint32_t ah[2][4], al[2][4], wh[4], wl[4];
            #pragma unroll
            for (int mi = 0; mi < 2; mi++) {
                const uint32_t off = (uint32_t)((warpM + mi * 16) * RS + kk * 16 + aRowOff) * 2;
                ldsm4(ah[mi], stg + O_AHI + off);
                ldsm4(al[mi], stg + O_ALO + off);
            }
            {
                const uint32_t off = (uint32_t)(warpN * RS + kk * 16 + wRowOff) * 2;
                ldsm4(wh, stg + O_WHI + off);
                ldsm4(wl, stg + O_WLO + off);
            }
            #pragma unroll
            for (int mi = 0; mi < 2; mi++)
                #pragma unroll
                for (int nj = 0; nj < 2; nj++)
                    mma16816(acc[mi][nj], ah[mi], &wh[nj * 2]);
            #pragma unroll
            for (int mi = 0; mi < 2; mi++)
                #pragma unroll
                for (int nj = 0; nj < 2; nj++)
                    mma16816(acc[mi][nj], al[mi], &wh[nj * 2]);
            #pragma unroll
            for (int mi = 0; mi < 2; mi++)
                #pragma unroll
                for (int nj = 0; nj < 2; nj++)
                    mma16816(acc[mi][nj], ah[mi], &wl[nj * 2]);
        }
        __syncthreads();   // compute(c) done before iter c+1 refills stage (c+4)%4 = c%4
    }

    // ---- fused LSTM epilogue ----
    // c-frag of m16n8: c0=(r,col), c1=(r,col+1), c2=(r+8,col), c3=(r+8,col+1),
    // r = lane>>2, col = (lane&3)*2. With col'=4j+g, lane pair (l, l^1) holds
    // all 4 gates of one hidden unit j; shfl_xor(1) exchanges the halves.
    const int q = lane & 3;
    #pragma unroll
    for (int mi = 0; mi < 2; mi++) {
        #pragma unroll
        for (int nj = 0; nj < 2; nj++) {
            float* cr = acc[mi][nj];
            const float e0 = __shfl_xor_sync(0xffffffffu, cr[0], 1);
            const float e1 = __shfl_xor_sync(0xffffffffu, cr[1], 1);
            const float e2 = __shfl_xor_sync(0xffffffffu, cr[2], 1);
            const float e3 = __shfl_xor_sync(0xffffffffu, cr[3], 1);
            const int nb = n0 + warpN + nj * 8 + (q >> 1) * 4;
            const float4 bb = *(const float4*)&g_br[nb];
            const int j = nb >> 2;
            float ri, rf, rg, ro;
            int m = m0 + warpM + mi * 16 + (lane >> 2);
            if ((lane & 1) == 0) { ri = cr[0]; rf = cr[1]; rg = e0;   ro = e1;   }
            else                 { ri = e2;    rf = e3;    rg = cr[2]; ro = cr[3]; m += 8; }
            const float ig = fsig (ri + bb.x);
            const float fg = fsig (rf + bb.y);
            const float gg = ftanh(rg + bb.z);
            const float og = fsig (ro + bb.w);
            const size_t idx = (size_t)m * Hq + j;
            const float cn = fg * g_c[idx] + ig * gg;
            g_c[idx] = cn;
            const float hv = og * ftanh(cn);
            const __nv_bfloat16 hh = __float2bfloat16(hv);
            hhi_o[idx] = hh;
            hlo_o[idx] = __float2bfloat16(hv - __bfloat162float(hh));
        }
    }
}

// out[b] = h_final[b,:] . W_out[0,:] + b_out[0]
__global__ void head_kernel(const float* __restrict__ Wout,
                            const float* __restrict__ bout,
                            float* __restrict__ out)
{
    const int b = blockIdx.x;
    const __nv_bfloat16* hi = g_hhi[0] + (size_t)b * Hq;   // T even -> final h in buffer 0
    const __nv_bfloat16* lo = g_hlo[0] + (size_t)b * Hq;
    float s = 0.0f;
    for (int k = threadIdx.x; k < Hq; k += blockDim.x)
        s += (__bfloat162float(hi[k]) + __bfloat162float(lo[k])) * Wout[k];
    __shared__ float red[32];
    #pragma unroll
    for (int o = 16; o; o >>= 1) s += __shfl_down_sync(0xffffffffu, s, o);
    if ((threadIdx.x & 31) == 0) red[threadIdx.x >> 5] = s;
    __syncthreads();
    if (threadIdx.x == 0)
        out[b] = red[0] + red[1] + red[2] + red[3] + bout[0];
}

extern "C" void kernel_launch(void* const* d_in, const int* in_sizes, int n_in,
                              void* d_out, int out_size)
{
    (void)in_sizes; (void)n_in; (void)out_size;
    const float* x    = (const float*)d_in[0];
    const float* Wih  = (const float*)d_in[1];
    const float* Whh  = (const float*)d_in[2];
    const float* bih  = (const float*)d_in[3];
    const float* bhh  = (const float*)d_in[4];
    const float* Wout = (const float*)d_in[5];
    const float* bout = (const float*)d_in[6];
    float* out = (float*)d_out;

    cudaFuncSetAttribute(lstm_step_kernel,
                         cudaFuncAttributeMaxDynamicSharedMemorySize, SMEM_BYTES);

    {
        const size_t n = (size_t)Bq * Tq * Fq;
        convert_x_kernel<<<(unsigned)((n + 255) / 256), 256>>>(x);
    }
    {
        const size_t n = (size_t)NG * KTOT;
        prep_w_kernel<<<(unsigned)((n + 255) / 256), 256>>>(Wih, Whh);
    }
    init_kernel<<<(Bq * Hq + 255) / 256, 256>>>(bih, bhh);

    dim3 grid(NG / TN, Bq / TM);   // (32, 8) = 256 CTAs -> 2 per SM
    for (int t = 0; t < Tq; t++)
        lstm_step_kernel<<<grid, NTH, SMEM_BYTES>>>(t);

    head_kernel<<<Bq, 128>>>(Wout, bout, out);
}

// round 14
// speedup vs baseline: 3.6432x; 1.1749x over previous
#include <cuda_runtime.h>
#include <cuda_bf16.h>
#include <cstdint>

// Problem constants
#define Bq   512
#define Tq   256
#define Fq   256
#define Hq   512
#define KTOT 768
#define NG   2048          // 4*Hq gate columns (reordered: col' = 4*j + gate)

// Step GEMM tiling (mma.sync path — baseline PTX, no sm_100a features)
#define TM   64            // batch rows per CTA
#define TN   64            // gate cols per CTA (= 16 hidden units)
#define KC   64            // K elements per chunk
#define NKC  12            // KTOT / KC
#define NTH  256
#define RS   72            // smem row stride in bf16 (144 B, conflict-free ldmatrix)
#define NSTG 2             // pipeline stages (prefetch depth 1; 1 barrier/chunk)

// Smem stage layout (bytes): Ahi | Alo | Whi | Wlo
#define A_BYTES (TM * RS * 2)          // 9216
#define W_BYTES (TN * RS * 2)          // 9216
#define O_AHI 0
#define O_ALO (A_BYTES)
#define O_WHI (2 * A_BYTES)
#define O_WLO (2 * A_BYTES + W_BYTES)
#define STAGE_BYTES (2 * A_BYTES + 2 * W_BYTES)   // 36864
#define SMEM_BYTES (NSTG * STAGE_BYTES)           // 73728 (2 CTAs/SM: 144K < 227K)

// ---------------- persistent device state (no allocs allowed) ----------------
__device__ __nv_bfloat16 g_xhi[(size_t)Bq * Tq * Fq];
__device__ __nv_bfloat16 g_xlo[(size_t)Bq * Tq * Fq];
__device__ __nv_bfloat16 g_hhi[2][Bq * Hq];
__device__ __nv_bfloat16 g_hlo[2][Bq * Hq];
__device__ float         g_c[Bq * Hq];
__device__ __nv_bfloat16 g_Whi[NG * KTOT];   // reordered [col'][k]
__device__ __nv_bfloat16 g_Wlo[NG * KTOT];
__device__ float         g_br[NG];           // reordered combined bias

// ---------------- helpers ----------------
__device__ __forceinline__ uint32_t smem_u32(const void* p) {
    uint32_t a;
    asm("{ .reg .u64 t; cvta.to.shared.u64 t, %1; cvt.u32.u64 %0, t; }" : "=r"(a) : "l"(p));
    return a;
}
#define CP16(dst, src) \
    asm volatile("cp.async.cg.shared.global [%0], [%1], 16;" :: "r"(dst), "l"(src) : "memory")
#define CP_COMMIT() asm volatile("cp.async.commit_group;" ::: "memory")
#define CP_WAIT0()  asm volatile("cp.async.wait_group 0;" ::: "memory")

__device__ __forceinline__ void ldsm4(uint32_t* r, uint32_t addr) {
    asm volatile("ldmatrix.sync.aligned.m8n8.x4.shared.b16 {%0,%1,%2,%3}, [%4];"
        : "=r"(r[0]), "=r"(r[1]), "=r"(r[2]), "=r"(r[3]) : "r"(addr));
}
__device__ __forceinline__ void mma16816(float* d, const uint32_t* a, const uint32_t* b) {
    asm volatile(
        "mma.sync.aligned.m16n8k16.row.col.f32.bf16.bf16.f32 "
        "{%0,%1,%2,%3}, {%4,%5,%6,%7}, {%8,%9}, {%0,%1,%2,%3};"
        : "+f"(d[0]), "+f"(d[1]), "+f"(d[2]), "+f"(d[3])
        : "r"(a[0]), "r"(a[1]), "r"(a[2]), "r"(a[3]), "r"(b[0]), "r"(b[1]));
}

__device__ __forceinline__ float fsig(float x)  { return 1.0f / (1.0f + __expf(-x)); }
__device__ __forceinline__ float ftanh(float x) { return 2.0f / (1.0f + __expf(-2.0f * x)) - 1.0f; }

// ---------------- prep kernels ----------------
__global__ void convert_x_kernel(const float* __restrict__ x) {
    size_t i = (size_t)blockIdx.x * blockDim.x + threadIdx.x;
    if (i >= (size_t)Bq * Tq * Fq) return;
    float v = x[i];
    __nv_bfloat16 hi = __float2bfloat16(v);
    g_xhi[i] = hi;
    g_xlo[i] = __float2bfloat16(v - __bfloat162float(hi));
}

__global__ void prep_w_kernel(const float* __restrict__ Wih, const float* __restrict__ Whh) {
    size_t i = (size_t)blockIdx.x * blockDim.x + threadIdx.x;
    if (i >= (size_t)NG * KTOT) return;
    int col = (int)(i / KTOT), k = (int)(i % KTOT);
    int r = (col & 3) * Hq + (col >> 2);            // original gate row (i,f,g,o blocks)
    float v = (k < Hq) ? Whh[(size_t)r * Hq + k] : Wih[(size_t)r * Fq + (k - Hq)];
    __nv_bfloat16 hi = __float2bfloat16(v);
    g_Whi[i] = hi;
    g_Wlo[i] = __float2bfloat16(v - __bfloat162float(hi));
}

__global__ void init_kernel(const float* __restrict__ bih, const float* __restrict__ bhh) {
    int i = blockIdx.x * blockDim.x + threadIdx.x;
    if (i < Bq * Hq) {
        g_hhi[0][i] = __float2bfloat16(0.0f);
        g_hlo[0][i] = __float2bfloat16(0.0f);
        g_c[i] = 0.0f;
    }
    if (i < NG) {
        int r = (i & 3) * Hq + (i >> 2);
        g_br[i] = bih[r] + bhh[r];
    }
}

// ---------------- chunk loader (cp.async, 16B segments) ----------------
// Per tile: 64 rows x 8 segs = 512 segs / 256 thr = 2 per thread. 8 cp.async/thread.
// KC=64 and Hq=512 -> chunks never straddle the h/x boundary (8 h-chunks, 4 x-chunks).
__device__ __forceinline__ void load_chunk(
    int c, int t, int m0, int n0, int tid, uint32_t sb,
    const __nv_bfloat16* __restrict__ hhi, const __nv_bfloat16* __restrict__ hlo)
{
    const int k0 = c * KC;
    const uint32_t stg = sb + (uint32_t)(c & (NSTG - 1)) * STAGE_BYTES;
    #pragma unroll
    for (int i = 0; i < 2; i++) {
        const int g = i * 256 + tid;
        const int row = g >> 3, seg = g & 7;
        const uint32_t d = (uint32_t)(row * (RS * 2) + seg * 16);
        // A: hi/lo
        {
            const __nv_bfloat16 *sh, *sl;
            if (k0 < Hq) {
                const size_t o = (size_t)(m0 + row) * Hq + k0 + seg * 8;
                sh = hhi + o; sl = hlo + o;
            } else {
                const size_t o = ((size_t)(m0 + row) * Tq + t) * Fq + (k0 - Hq) + seg * 8;
                sh = g_xhi + o; sl = g_xlo + o;
            }
            CP16(stg + O_AHI + d, sh);
            CP16(stg + O_ALO + d, sl);
        }
        // W: hi/lo
        {
            const size_t o = (size_t)(n0 + row) * KTOT + k0 + seg * 8;
            CP16(stg + O_WHI + d, g_Whi + o);
            CP16(stg + O_WLO + d, g_Wlo + o);
        }
    }
    CP_COMMIT();
}

// ---------------- LSTM step: mma.sync bf16-split GEMM + fused epilogue ----------------
// Grid (32, 8) = 256 CTAs, 2/SM. 8 warps: warpM=(wid&1)*32, warpN=(wid>>1)*16.
// ONE barrier per chunk: wait_group(0) -> bar -> issue load(c+1) -> compute(c).
// The barrier certifies (a) every thread's chunk-c copies landed (own wait0
// precedes it) and (b) all warps finished compute(c-1), so load(c+1) writing
// stage (c+1)&1 = (c-1)&1 is race-free.
__global__ __launch_bounds__(NTH, 2)
void lstm_step_kernel(int t)
{
    extern __shared__ char dyn_smem[];
    const uint32_t sb = smem_u32(dyn_smem);
    const int tid  = threadIdx.x;
    const int wid  = tid >> 5;
    const int lane = tid & 31;
    const int warpM = (wid & 1) * 32;
    const int warpN = (wid >> 1) * 16;

    const int m0 = blockIdx.y * TM;
    const int n0 = blockIdx.x * TN;

    const __nv_bfloat16* __restrict__ hhi = g_hhi[t & 1];
    const __nv_bfloat16* __restrict__ hlo = g_hlo[t & 1];
    __nv_bfloat16* __restrict__ hhi_o = g_hhi[(t + 1) & 1];
    __nv_bfloat16* __restrict__ hlo_o = g_hlo[(t + 1) & 1];

    float acc[2][2][4];
    #pragma unroll
    for (int mi = 0; mi < 2; mi++)
        #pragma unroll
        for (int nj = 0; nj < 2; nj++)
            #pragma unroll
            for (int r = 0; r < 4; r++) acc[mi][nj][r] = 0.0f;

    // Prologue: load chunk 0
    load_chunk(0, t, m0, n0, tid, sb, hhi, hlo);

    // Precomputed per-warp ldsm address offsets (element indices)
    const int aRowOff = (lane & 15) * RS + (lane >> 4) * 8;          // + mi*16*RS + kk*16
    const int wRowOff = (((lane >> 4) & 1) * 8 + (lane & 7)) * RS + ((lane >> 3) & 1) * 8;

    for (int c = 0; c < NKC; c++) {
        CP_WAIT0();        // own chunk-c copies (and any older) done
        __syncthreads();   // all threads' copies visible; all finished compute(c-1)
        if (c + 1 < NKC) load_chunk(c + 1, t, m0, n0, tid, sb, hhi, hlo);

        const uint32_t stg = sb + (uint32_t)(c & (NSTG - 1)) * STAGE_BYTES;
        #pragma unroll
        for (int kk = 0; kk < 4; kk++) {
            uint32_t ah[2][4], al[2][4], wh[4], wl[4];
            #pragma unroll
            for (int mi = 0; mi < 2; mi++) {
                const uint32_t off = (uint32_t)((warpM + mi * 16) * RS + kk * 16 + aRowOff) * 2;
                ldsm4(ah[mi], stg + O_AHI + off);
                ldsm4(al[mi], stg + O_ALO + off);
            }
            {
                const uint32_t off = (uint32_t)(warpN * RS + kk * 16 + wRowOff) * 2;
                ldsm4(wh, stg + O_WHI + off);
                ldsm4(wl, stg + O_WLO + off);
            }
            #pragma unroll
            for (int mi = 0; mi < 2; mi++)
                #pragma unroll
                for (int nj = 0; nj < 2; nj++)
                    mma16816(acc[mi][nj], ah[mi], &wh[nj * 2]);
            #pragma unroll
            for (int mi = 0; mi < 2; mi++)
                #pragma unroll
                for (int nj = 0; nj < 2; nj++)
                    mma16816(acc[mi][nj], al[mi], &wh[nj * 2]);
            #pragma unroll
            for (int mi = 0; mi < 2; mi++)
                #pragma unroll
                for (int nj = 0; nj < 2; nj++)
                    mma16816(acc[mi][nj], ah[mi], &wl[nj * 2]);
        }
    }

    // ---- fused LSTM epilogue ----
    // c-frag of m16n8: c0=(r,col), c1=(r,col+1), c2=(r+8,col), c3=(r+8,col+1),
    // r = lane>>2, col = (lane&3)*2. With col'=4j+g, lane pair (l, l^1) holds
    // all 4 gates of one hidden unit j; shfl_xor(1) exchanges the halves.
    const int q = lane & 3;
    #pragma unroll
    for (int mi = 0; mi < 2; mi++) {
        #pragma unroll
        for (int nj = 0; nj < 2; nj++) {
            float* cr = acc[mi][nj];
            const float e0 = __shfl_xor_sync(0xffffffffu, cr[0], 1);
            const float e1 = __shfl_xor_sync(0xffffffffu, cr[1], 1);
            const float e2 = __shfl_xor_sync(0xffffffffu, cr[2], 1);
            const float e3 = __shfl_xor_sync(0xffffffffu, cr[3], 1);
            const int nb = n0 + warpN + nj * 8 + (q >> 1) * 4;
            const float4 bb = *(const float4*)&g_br[nb];
            const int j = nb >> 2;
            float ri, rf, rg, ro;
            int m = m0 + warpM + mi * 16 + (lane >> 2);
            if ((lane & 1) == 0) { ri = cr[0]; rf = cr[1]; rg = e0;   ro = e1;   }
            else                 { ri = e2;    rf = e3;    rg = cr[2]; ro = cr[3]; m += 8; }
            const float ig = fsig (ri + bb.x);
            const float fg = fsig (rf + bb.y);
            const float gg = ftanh(rg + bb.z);
            const float og = fsig (ro + bb.w);
            const size_t idx = (size_t)m * Hq + j;
            const float cn = fg * g_c[idx] + ig * gg;
            g_c[idx] = cn;
            const float hv = og * ftanh(cn);
            const __nv_bfloat16 hh = __float2bfloat16(hv);
            hhi_o[idx] = hh;
            hlo_o[idx] = __float2bfloat16(hv - __bfloat162float(hh));
        }
    }
}

// out[b] = h_final[b,:] . W_out[0,:] + b_out[0]
__global__ void head_kernel(const float* __restrict__ Wout,
                            const float* __restrict__ bout,
                            float* __restrict__ out)
{
    const int b = blockIdx.x;
    const __nv_bfloat16* hi = g_hhi[0] + (size_t)b * Hq;   // T even -> final h in buffer 0
    const __nv_bfloat16* lo = g_hlo[0] + (size_t)b * Hq;
    float s = 0.0f;
    for (int k = threadIdx.x; k < Hq; k += blockDim.x)
        s += (__bfloat162float(hi[k]) + __bfloat162float(lo[k])) * Wout[k];
    __shared__ float red[32];
    #pragma unroll
    for (int o = 16; o; o >>= 1) s += __shfl_down_sync(0xffffffffu, s, o);
    if ((threadIdx.x & 31) == 0) red[threadIdx.x >> 5] = s;
    __syncthreads();
    if (threadIdx.x == 0)
        out[b] = red[0] + red[1] + red[2] + red[3] + bout[0];
}

extern "C" void kernel_launch(void* const* d_in, const int* in_sizes, int n_in,
                              void* d_out, int out_size)
{
    (void)in_sizes; (void)n_in; (void)out_size;
    const float* x    = (const float*)d_in[0];
    const float* Wih  = (const float*)d_in[1];
    const float* Whh  = (const float*)d_in[2];
    const float* bih  = (const float*)d_in[3];
    const float* bhh  = (const float*)d_in[4];
    const float* Wout = (const float*)d_in[5];
    const float* bout = (const float*)d_in[6];
    float* out = (float*)d_out;

    cudaFuncSetAttribute(lstm_step_kernel,
                         cudaFuncAttributeMaxDynamicSharedMemorySize, SMEM_BYTES);

    {
        const size_t n = (size_t)Bq * Tq * Fq;
        convert_x_kernel<<<(unsigned)((n + 255) / 256), 256>>>(x);
    }
    {
        const size_t n = (size_t)NG * KTOT;
        prep_w_kernel<<<(unsigned)((n + 255) / 256), 256>>>(Wih, Whh);
    }
    init_kernel<<<(Bq * Hq + 255) / 256, 256>>>(bih, bhh);

    dim3 grid(NG / TN, Bq / TM);   // (32, 8) = 256 CTAs -> 2 per SM
    for (int t = 0; t < Tq; t++)
        lstm_step_kernel<<<grid, NTH, SMEM_BYTES>>>(t);

    head_kernel<<<Bq, 128>>>(Wout, bout, out);
}